// round 7
// baseline (speedup 1.0000x reference)
#include <cuda_runtime.h>
#include <math.h>

#define NN 50000
#define NE 1600000
#define NF 256
#define NH 128
#define NC 40

// ---------------- scratch (no allocations allowed) ----------------
__device__ float g_deg[NN];
__device__ float g_dinv[NN];
__device__ float g_G1[(size_t)NN * NH];   // layer1 g = dinv*(xW1); later reused as H1
__device__ float g_AGG1[(size_t)NN * NH]; // layer1 aggregation target
__device__ float g_G2[(size_t)NN * NC];   // layer2 g = dinv*(H1 W2)

// ---------------- degree / dinv ----------------
__global__ void k_deg_init() {
    int v = blockIdx.x * 256 + threadIdx.x;
    if (v < NN) g_deg[v] = 1.0f;  // self-loop
}

__global__ void k_deg_count(const int* __restrict__ dst) {
    int e = blockIdx.x * 256 + threadIdx.x;
    if (e < NE) atomicAdd(&g_deg[dst[e]], 1.0f);
}

__global__ void k_dinv() {
    int v = blockIdx.x * 256 + threadIdx.x;
    if (v < NN) g_dinv[v] = 1.0f / sqrtf(g_deg[v]);
}

// ---------------- GEMM1: G1 = dinv * (X @ W1), also AGG1 = G1 ----------------
// block: 256 threads, tile 128 rows x 128 cols, 8x8 per thread, K-step 8
__global__ __launch_bounds__(256) void k_gemm1(const float* __restrict__ x,
                                               const float* __restrict__ W1) {
    __shared__ float xs[128 * 8];   // [row][kk]
    __shared__ float ws[8 * 128];   // [kk][col]
    const int tid = threadIdx.x;
    const int txc = tid & 15;       // col-octet: cols txc*8 .. +8
    const int tyr = tid >> 4;       // 0..15 ; rows tyr + 16*r
    const int row0 = blockIdx.x * 128;

    float acc[8][8];
#pragma unroll
    for (int r = 0; r < 8; r++)
#pragma unroll
        for (int c = 0; c < 8; c++) acc[r][c] = 0.f;

    const int xi = tid * 4;             // 0..1020
    const int xrow = xi >> 3;           // 0..127
    const int xkk = xi & 7;             // 0 or 4
    const int gxr = min(row0 + xrow, NN - 1);
    const int wkk = tid >> 5;           // 0..7
    const int wcol = (tid & 31) * 4;

    for (int k0 = 0; k0 < NF; k0 += 8) {
        float4 xv = *(const float4*)&x[(size_t)gxr * NF + k0 + xkk];
        float4 wv = *(const float4*)&W1[(size_t)(k0 + wkk) * NH + wcol];
        __syncthreads();
        *(float4*)&xs[xrow * 8 + xkk] = xv;
        *(float4*)&ws[wkk * 128 + wcol] = wv;
        __syncthreads();
#pragma unroll
        for (int kk = 0; kk < 8; kk++) {
            float4 wa = *(float4*)&ws[kk * 128 + txc * 8];
            float4 wb = *(float4*)&ws[kk * 128 + txc * 8 + 4];
#pragma unroll
            for (int r = 0; r < 8; r++) {
                float xvv = xs[(tyr + 16 * r) * 8 + kk];
                acc[r][0] += xvv * wa.x; acc[r][1] += xvv * wa.y;
                acc[r][2] += xvv * wa.z; acc[r][3] += xvv * wa.w;
                acc[r][4] += xvv * wb.x; acc[r][5] += xvv * wb.y;
                acc[r][6] += xvv * wb.z; acc[r][7] += xvv * wb.w;
            }
        }
    }
#pragma unroll
    for (int r = 0; r < 8; r++) {
        int gr = row0 + tyr + 16 * r;
        if (gr < NN) {
            float dv = g_dinv[gr];
            float4 a, b;
            a.x = acc[r][0] * dv; a.y = acc[r][1] * dv;
            a.z = acc[r][2] * dv; a.w = acc[r][3] * dv;
            b.x = acc[r][4] * dv; b.y = acc[r][5] * dv;
            b.z = acc[r][6] * dv; b.w = acc[r][7] * dv;
            size_t off = (size_t)gr * NH + txc * 8;
            *(float4*)&g_G1[off] = a;     *(float4*)&g_G1[off + 4] = b;
            *(float4*)&g_AGG1[off] = a;   *(float4*)&g_AGG1[off + 4] = b;
        }
    }
}

// ---------------- scatter layer1: warp per edge, lane = float4 chunk ----------------
__global__ void k_scatter1(const int* __restrict__ src,
                           const int* __restrict__ dst) {
    unsigned idx = blockIdx.x * 256u + threadIdx.x;
    unsigned e = idx >> 5;
    if (e >= NE) return;
    unsigned c = (idx & 31) << 2;   // float offset 0..124
    int s = __ldg(&src[e]);
    int d = __ldg(&dst[e]);
    const float4 g = *(const float4*)&g_G1[(size_t)s * NH + c];
    float* p = &g_AGG1[(size_t)d * NH + c];
    asm volatile("red.global.add.v4.f32 [%0], {%1,%2,%3,%4};"
                 :: "l"(p), "f"(g.x), "f"(g.y), "f"(g.z), "f"(g.w) : "memory");
}

// ---------------- post layer1: H1 = relu(dinv*AGG1 + b1) * drop_mask (into g_G1) ----------------
__global__ void k_post1(const float* __restrict__ b1, const float* __restrict__ mask) {
    unsigned idx = blockIdx.x * 256u + threadIdx.x;
    if (idx >= (unsigned)(NN * NH / 4)) return;
    unsigned i = idx << 2;
    unsigned v = i >> 7;       // /128
    unsigned j = i & 127;
    float dv = g_dinv[v];
    float4 a = *(float4*)&g_AGG1[i];
    float4 b = *(const float4*)&b1[j];
    float4 m = *(const float4*)&mask[i];
    float4 h;
    h.x = fmaxf(fmaf(a.x, dv, b.x), 0.f) * m.x;
    h.y = fmaxf(fmaf(a.y, dv, b.y), 0.f) * m.y;
    h.z = fmaxf(fmaf(a.z, dv, b.z), 0.f) * m.z;
    h.w = fmaxf(fmaf(a.w, dv, b.w), 0.f) * m.w;
    *(float4*)&g_G1[i] = h;
}

// ---------------- GEMM2: G2 = dinv * (H1 @ W2), also out = G2 (self-loop init) ----------------
// block: 320 threads, tile 128 rows x 40 cols; thread = (col quad cg, row group rg), 4 rows x 4 cols
__global__ __launch_bounds__(320) void k_gemm2(const float* __restrict__ W2,
                                               float* __restrict__ out) {
    __shared__ float ws[NH * NC];  // 20 KB
    const int tid = threadIdx.x;
    for (int i = tid; i < NH * NC; i += 320) ws[i] = W2[i];
    __syncthreads();

    const int cg = tid % 10;       // cols cg*4 .. +4
    const int rg = tid / 10;       // 0..31
    const int row0 = blockIdx.x * 128;

    float acc[4][4];
#pragma unroll
    for (int r = 0; r < 4; r++)
#pragma unroll
        for (int c = 0; c < 4; c++) acc[r][c] = 0.f;

    int grc[4];
#pragma unroll
    for (int r = 0; r < 4; r++) grc[r] = min(row0 + rg + 32 * r, NN - 1);

    for (int k0 = 0; k0 < NH; k0 += 4) {
        float4 hv[4];
#pragma unroll
        for (int r = 0; r < 4; r++)
            hv[r] = *(const float4*)&g_G1[(size_t)grc[r] * NH + k0];
#pragma unroll
        for (int kk = 0; kk < 4; kk++) {
            float4 w = *(float4*)&ws[(k0 + kk) * NC + cg * 4];
#pragma unroll
            for (int r = 0; r < 4; r++) {
                float xv = (kk == 0) ? hv[r].x : (kk == 1) ? hv[r].y
                         : (kk == 2) ? hv[r].z : hv[r].w;
                acc[r][0] += xv * w.x; acc[r][1] += xv * w.y;
                acc[r][2] += xv * w.z; acc[r][3] += xv * w.w;
            }
        }
    }
#pragma unroll
    for (int r = 0; r < 4; r++) {
        int gr = row0 + rg + 32 * r;
        if (gr < NN) {
            float dv = g_dinv[gr];
            float4 o;
            o.x = acc[r][0] * dv; o.y = acc[r][1] * dv;
            o.z = acc[r][2] * dv; o.w = acc[r][3] * dv;
            size_t off = (size_t)gr * NC + cg * 4;
            *(float4*)&g_G2[off] = o;
            *(float4*)&out[off] = o;
        }
    }
}

// ---------------- scatter layer2: thread = (edge, float4 chunk of 10) ----------------
__global__ void k_scatter2(const int* __restrict__ src,
                           const int* __restrict__ dst,
                           float* __restrict__ out) {
    unsigned idx = blockIdx.x * 256u + threadIdx.x;
    if (idx >= (unsigned)NE * 10u) return;
    unsigned e = idx / 10u;
    unsigned c = (idx - e * 10u) << 2;   // float offset 0..36
    int s = __ldg(&src[e]);
    int d = __ldg(&dst[e]);
    const float4 g = *(const float4*)&g_G2[(size_t)s * NC + c];
    float* p = &out[(size_t)d * NC + c];
    asm volatile("red.global.add.v4.f32 [%0], {%1,%2,%3,%4};"
                 :: "l"(p), "f"(g.x), "f"(g.y), "f"(g.z), "f"(g.w) : "memory");
}

// ---------------- final: out = log_softmax(dinv*AGG2 + b2), in place, warp per row ----------------
__global__ void k_lsm(const float* __restrict__ b2, float* __restrict__ out) {
    int warp = (blockIdx.x * blockDim.x + threadIdx.x) >> 5;
    int lane = threadIdx.x & 31;
    if (warp >= NN) return;
    float dv = g_dinv[warp];
    size_t base = (size_t)warp * NC;
    float v0 = fmaf(dv, out[base + lane], b2[lane]);
    float v1 = -1e30f;
    if (lane < NC - 32) v1 = fmaf(dv, out[base + 32 + lane], b2[32 + lane]);
    float m = fmaxf(v0, v1);
#pragma unroll
    for (int o = 16; o; o >>= 1) m = fmaxf(m, __shfl_xor_sync(0xFFFFFFFFu, m, o));
    float s = expf(v0 - m) + ((lane < NC - 32) ? expf(v1 - m) : 0.f);
#pragma unroll
    for (int o = 16; o; o >>= 1) s += __shfl_xor_sync(0xFFFFFFFFu, s, o);
    float l = m + logf(s);
    out[base + lane] = v0 - l;
    if (lane < NC - 32) out[base + 32 + lane] = v1 - l;
}

// ---------------- launch ----------------
extern "C" void kernel_launch(void* const* d_in, const int* in_sizes, int n_in,
                              void* d_out, int out_size) {
    const float* x    = (const float*)d_in[0];
    const int*   ei   = (const int*)d_in[1];   // edge_index: int32 (JAX x64 disabled)
    const float* W1   = (const float*)d_in[2];
    const float* b1   = (const float*)d_in[3];
    const float* W2   = (const float*)d_in[4];
    const float* b2   = (const float*)d_in[5];
    const float* mask = (const float*)d_in[6];
    float*       out  = (float*)d_out;

    const int* src = ei;
    const int* dst = ei + NE;

    k_deg_init <<<(NN + 255) / 256, 256>>>();
    k_deg_count<<<(NE + 255) / 256, 256>>>(dst);
    k_dinv     <<<(NN + 255) / 256, 256>>>();

    k_gemm1    <<<(NN + 127) / 128, 256>>>(x, W1);
    k_scatter1 <<<(NE * 32u + 255) / 256, 256>>>(src, dst);
    k_post1    <<<(NN * NH / 4 + 255) / 256, 256>>>(b1, mask);

    k_gemm2    <<<(NN + 127) / 128, 320>>>(W2, out);
    k_scatter2 <<<((unsigned)NE * 10u + 255) / 256, 256>>>(src, dst, out);

    k_lsm      <<<(NN * 32 + 127) / 128, 128>>>(b2, out);
}